// round 3
// baseline (speedup 1.0000x reference)
#include <cuda_runtime.h>
#include <math_constants.h>

#define N_CODES 4096
#define DIM 64
#define TILE_CODES 128
#define BLOCK_THREADS 128

// ---------- packed f32x2 helpers (FFMA2 path; only reachable via PTX) ----------
__device__ __forceinline__ unsigned long long pack2(float lo, float hi) {
    unsigned long long r;
    asm("mov.b64 %0, {%1, %2};" : "=l"(r) : "f"(lo), "f"(hi));
    return r;
}
__device__ __forceinline__ void unpack2(unsigned long long v, float& lo, float& hi) {
    asm("mov.b64 {%0, %1}, %2;" : "=f"(lo), "=f"(hi) : "l"(v));
}
#define FMA_F32X2(d, a, b, c) \
    asm("fma.rn.f32x2 %0, %1, %2, %3;" : "=l"(d) : "l"(a), "l"(b), "l"(c))
#define ADD_F32X2(d, a, b) \
    asm("add.rn.f32x2 %0, %1, %2;" : "=l"(d) : "l"(a), "l"(b))

// scratch: ||w_j||^2 per codebook row (no allocs allowed -> device global)
__device__ float g_wsq[N_CODES];

// ---------- kernel 1: codebook squared norms ----------
__global__ void wsq_kernel(const float* __restrict__ w) {
    int j = blockIdx.x * blockDim.x + threadIdx.x;
    if (j < N_CODES) {
        const float4* wr = reinterpret_cast<const float4*>(w + (size_t)j * DIM);
        float s = 0.f;
#pragma unroll
        for (int k = 0; k < DIM / 4; k++) {
            float4 v = wr[k];
            s += v.x * v.x + v.y * v.y + v.z * v.z + v.w * v.w;
        }
        g_wsq[j] = s;
    }
}

// ---------- kernel 2: nearest-codeword search + gather ----------
// score_j = ||w_j||^2 - 2 * <x, w_j>   (||x||^2 dropped: argmin-invariant)
__global__ __launch_bounds__(BLOCK_THREADS)
void vq_kernel(const float* __restrict__ x,
               const float* __restrict__ w,
               float* __restrict__ out_data,
               float* __restrict__ out_idx) {
    __shared__ float s_w[TILE_CODES * DIM];     // 32 KB
    __shared__ float s_wsq[TILE_CODES];

    const int row = blockIdx.x * BLOCK_THREADS + threadIdx.x;

    // x row -> registers as 32 packed f32x2
    unsigned long long xv[DIM / 2];
    {
        const float4* xr = reinterpret_cast<const float4*>(x + (size_t)row * DIM);
#pragma unroll
        for (int k = 0; k < DIM / 4; k++) {
            float4 v = xr[k];
            xv[2 * k]     = pack2(v.x, v.y);
            xv[2 * k + 1] = pack2(v.z, v.w);
        }
    }

    float best = CUDART_INF_F;
    int bestj = 0;

    for (int t = 0; t < N_CODES; t += TILE_CODES) {
        __syncthreads();
        // cooperative tile load: TILE_CODES*DIM floats = 2048 float4 / 128 thr = 16 each
        {
            const float4* src = reinterpret_cast<const float4*>(w + (size_t)t * DIM);
            float4* dst = reinterpret_cast<float4*>(s_w);
#pragma unroll
            for (int i = 0; i < (TILE_CODES * DIM / 4) / BLOCK_THREADS; i++) {
                int idx = threadIdx.x + i * BLOCK_THREADS;
                dst[idx] = src[idx];
            }
            if (threadIdx.x < TILE_CODES)
                s_wsq[threadIdx.x] = g_wsq[t + threadIdx.x];
        }
        __syncthreads();

#pragma unroll 2
        for (int jj = 0; jj < TILE_CODES; jj++) {
            // row = 64 floats = 16 ulonglong2 (each = 4 floats = 2 packed f32x2)
            const ulonglong2* wp =
                reinterpret_cast<const ulonglong2*>(s_w + jj * DIM);
            unsigned long long a0 = 0ull, a1 = 0ull, a2 = 0ull, a3 = 0ull;
#pragma unroll
            for (int k = 0; k < 16; k += 2) {        // 16 LDS.128, 32 FFMA2 (full 64 dims)
                ulonglong2 w01 = wp[k];
                ulonglong2 w23 = wp[k + 1];
                FMA_F32X2(a0, xv[2 * k],     w01.x, a0);
                FMA_F32X2(a1, xv[2 * k + 1], w01.y, a1);
                FMA_F32X2(a2, xv[2 * k + 2], w23.x, a2);
                FMA_F32X2(a3, xv[2 * k + 3], w23.y, a3);
            }
            ADD_F32X2(a0, a0, a1);
            ADD_F32X2(a2, a2, a3);
            ADD_F32X2(a0, a0, a2);
            float lo, hi;
            unpack2(a0, lo, hi);
            float dot = lo + hi;
            float score = s_wsq[jj] - 2.0f * dot;
            if (score < best) {      // strict '<' keeps lowest index on ties (matches argmin)
                best = score;
                bestj = t + jj;
            }
        }
    }

    // gather winning codeword
    {
        const float4* wr = reinterpret_cast<const float4*>(w + (size_t)bestj * DIM);
        float4* orow = reinterpret_cast<float4*>(out_data + (size_t)row * DIM);
#pragma unroll
        for (int k = 0; k < DIM / 4; k++) orow[k] = wr[k];
    }
    if (out_idx) out_idx[row] = (float)bestj;
}

extern "C" void kernel_launch(void* const* d_in, const int* in_sizes, int n_in,
                              void* d_out, int out_size) {
    const float* x = (const float*)d_in[0];
    const float* w = (const float*)d_in[1];
    float* out = (float*)d_out;

    const int n_rows = in_sizes[0] / DIM;   // 65536

    wsq_kernel<<<(N_CODES + 255) / 256, 256>>>(w);

    // second output region (q_idx) if the flattened out buffer carries it
    float* out_idx = nullptr;
    if ((size_t)out_size >= (size_t)n_rows * DIM + (size_t)n_rows)
        out_idx = out + (size_t)n_rows * DIM;

    vq_kernel<<<n_rows / BLOCK_THREADS, BLOCK_THREADS>>>(x, w, out, out_idx);
}

// round 5
// speedup vs baseline: 3.0483x; 3.0483x over previous
#include <cuda_runtime.h>
#include <cuda_bf16.h>
#include <math_constants.h>
#include <cstdint>

#define N_CODES 4096
#define DIM 64
#define TILE_N 128
#define NT (N_CODES / TILE_N)
#define WARPS 4
#define BLOCK_THREADS (WARPS * 32)
#define ROWS_PER_WARP 32
#define ROWS_PER_CTA (WARPS * ROWS_PER_WARP)   // 128
#define WPAD 72                                 // padded smem row (bf16 elems) -> conflict-free LDSM
#define DELTA 1e-4f

// ---------------- device scratch (no allocs allowed) ----------------
__device__ float g_wsq[N_CODES];
__device__ __align__(16) __nv_bfloat16 g_w1[N_CODES * DIM];
__device__ __align__(16) __nv_bfloat16 g_w2[N_CODES * DIM];
__device__ int g_nflag;
__device__ int g_flagrows[65536];

// ---------------- kernel 1: prep (wsq, bf16 hi/lo codebook split, flag reset) ----------------
__global__ void prep_kernel(const float* __restrict__ w) {
    int j = blockIdx.x * blockDim.x + threadIdx.x;
    if (j == 0) g_nflag = 0;
    if (j < N_CODES) {
        float s = 0.f;
#pragma unroll
        for (int k = 0; k < DIM; k++) {
            float v = w[(size_t)j * DIM + k];
            s += v * v;
            __nv_bfloat16 h1 = __float2bfloat16(v);
            float r = v - __bfloat162float(h1);
            g_w1[(size_t)j * DIM + k] = h1;
            g_w2[(size_t)j * DIM + k] = __float2bfloat16(r);
        }
        g_wsq[j] = s;
    }
}

// ---------------- mma / ldmatrix wrappers (family-portable PTX) ----------------
__device__ __forceinline__ void mma_16816(float c[4], const uint32_t a[4],
                                          uint32_t b0, uint32_t b1) {
    asm volatile(
        "mma.sync.aligned.m16n8k16.row.col.f32.bf16.bf16.f32 "
        "{%0,%1,%2,%3}, {%4,%5,%6,%7}, {%8,%9}, {%0,%1,%2,%3};"
        : "+f"(c[0]), "+f"(c[1]), "+f"(c[2]), "+f"(c[3])
        : "r"(a[0]), "r"(a[1]), "r"(a[2]), "r"(a[3]), "r"(b0), "r"(b1));
}
__device__ __forceinline__ void ldsm_x2(uint32_t& r0, uint32_t& r1, uint32_t saddr) {
    asm volatile("ldmatrix.sync.aligned.m8n8.x2.shared.b16 {%0,%1}, [%2];"
                 : "=r"(r0), "=r"(r1) : "r"(saddr));
}
__device__ __forceinline__ uint32_t pack_bf16x2(float lo, float hi) {
    __nv_bfloat162 t = __floats2bfloat162_rn(lo, hi);
    return *reinterpret_cast<uint32_t*>(&t);
}

// ---------------- kernel 2: fused bf16x2 mma.sync GEMM + argmin ----------------
__global__ __launch_bounds__(BLOCK_THREADS)
void vq_main(const float* __restrict__ x, const float* __restrict__ w,
             float* __restrict__ out, float* __restrict__ out_idx) {
    __shared__ __nv_bfloat16 ws1[TILE_N * WPAD];
    __shared__ __nv_bfloat16 ws2[TILE_N * WPAD];
    __shared__ float s_wsq[TILE_N];
    __shared__ int s_bj[WARPS][ROWS_PER_WARP];
    __shared__ unsigned char s_fl[WARPS][ROWS_PER_WARP];

    const int tid = threadIdx.x, lane = tid & 31, wid = tid >> 5;
    const int ctarow = blockIdx.x * ROWS_PER_CTA;
    const int wrow = ctarow + wid * ROWS_PER_WARP;

    // ---- A fragments: 2 row-sets x 4 k-chunks x 4 regs, hi + lo splits ----
    uint32_t A1[2][4][4], A2[2][4][4];
#pragma unroll
    for (int s = 0; s < 2; s++)
#pragma unroll
        for (int kc = 0; kc < 4; kc++)
#pragma unroll
            for (int f = 0; f < 4; f++) {
                int r = wrow + s * 16 + (lane >> 2) + (f & 1) * 8;
                int c = kc * 16 + (lane & 3) * 2 + (f >> 1) * 8;
                float2 v = *(const float2*)(x + (size_t)r * DIM + c);
                __nv_bfloat162 h1 = __floats2bfloat162_rn(v.x, v.y);
                float rx = v.x - __bfloat162float(h1.x);
                float ry = v.y - __bfloat162float(h1.y);
                A1[s][kc][f] = *reinterpret_cast<uint32_t*>(&h1);
                A2[s][kc][f] = pack_bf16x2(rx, ry);
            }

    // per-thread rows: 0: wrow+lane/4, 1: +8, 2: +16, 3: +24
    float bv[4] = {CUDART_INF_F, CUDART_INF_F, CUDART_INF_F, CUDART_INF_F};
    float b2v[4] = {CUDART_INF_F, CUDART_INF_F, CUDART_INF_F, CUDART_INF_F};
    int bj[4] = {0, 0, 0, 0};

    const int l16 = lane & 15;
    const uint32_t sb1 = (uint32_t)__cvta_generic_to_shared(ws1);
    const uint32_t sb2 = (uint32_t)__cvta_generic_to_shared(ws2);
    const uint32_t ldsm_toff = (uint32_t)((l16 & 7) * (WPAD * 2) + (l16 >> 3) * 16);

    for (int t = 0; t < NT; t++) {
        __syncthreads();
        // load 128-code tile of both splits into padded smem (8 uint4 per thread per split)
        const uint4* gw1 = (const uint4*)(g_w1 + (size_t)t * TILE_N * DIM);
        const uint4* gw2 = (const uint4*)(g_w2 + (size_t)t * TILE_N * DIM);
#pragma unroll
        for (int i = 0; i < 8; i++) {
            int g = tid + i * BLOCK_THREADS;       // 0..1023 (uint4 units)
            int c = g >> 3, q = g & 7;
            *(uint4*)((char*)ws1 + c * (WPAD * 2) + q * 16) = gw1[g];
            *(uint4*)((char*)ws2 + c * (WPAD * 2) + q * 16) = gw2[g];
        }
        if (tid < TILE_N) s_wsq[tid] = g_wsq[t * TILE_N + tid];
        __syncthreads();

        for (int nb = 0; nb < TILE_N / 8; nb++) {
            float acc[2][4] = {{0.f, 0.f, 0.f, 0.f}, {0.f, 0.f, 0.f, 0.f}};
            uint32_t nboff = (uint32_t)(nb * 8 * (WPAD * 2)) + ldsm_toff;
#pragma unroll
            for (int kc = 0; kc < 4; kc++) {
                uint32_t b1a, b1b, b2a, b2b;
                uint32_t koff = nboff + kc * 32;
                ldsm_x2(b1a, b1b, sb1 + koff);
                ldsm_x2(b2a, b2b, sb2 + koff);
#pragma unroll
                for (int s = 0; s < 2; s++) {
                    mma_16816(acc[s], A1[s][kc], b1a, b1b);   // x1.w1
                    mma_16816(acc[s], A1[s][kc], b2a, b2b);   // x1.w2
                    mma_16816(acc[s], A2[s][kc], b1a, b1b);   // x2.w1
                    mma_16816(acc[s], A2[s][kc], b2a, b2b);   // x2.w2
                }
            }
            // epilogue: scores = wsq - 2*dot ; C layout: c0 (r, n0), c1 (r, n0+1), c2 (r+8, n0), c3 (r+8, n0+1)
            int nloc = nb * 8 + (lane & 3) * 2;
            int n0 = t * TILE_N + nloc;
            float2 wq = *(const float2*)&s_wsq[nloc];
#pragma unroll
            for (int s = 0; s < 2; s++) {
                float s0 = fmaf(-2.f, acc[s][0], wq.x);
                float s1 = fmaf(-2.f, acc[s][1], wq.y);
                float s2 = fmaf(-2.f, acc[s][2], wq.x);
                float s3 = fmaf(-2.f, acc[s][3], wq.y);
                int r0 = 2 * s, r1 = 2 * s + 1;
                if (s0 < bv[r0]) { b2v[r0] = bv[r0]; bv[r0] = s0; bj[r0] = n0; }
                else             { b2v[r0] = fminf(b2v[r0], s0); }
                if (s1 < bv[r0]) { b2v[r0] = bv[r0]; bv[r0] = s1; bj[r0] = n0 + 1; }
                else             { b2v[r0] = fminf(b2v[r0], s1); }
                if (s2 < bv[r1]) { b2v[r1] = bv[r1]; bv[r1] = s2; bj[r1] = n0; }
                else             { b2v[r1] = fminf(b2v[r1], s2); }
                if (s3 < bv[r1]) { b2v[r1] = bv[r1]; bv[r1] = s3; bj[r1] = n0 + 1; }
                else             { b2v[r1] = fminf(b2v[r1], s3); }
            }
        }
    }

    // ---- quad reduce (threads sharing same rows differ only in lane&3) ----
#pragma unroll
    for (int off = 1; off <= 2; off <<= 1) {
#pragma unroll
        for (int i = 0; i < 4; i++) {
            float ob  = __shfl_xor_sync(0xffffffffu, bv[i], off);
            float ob2 = __shfl_xor_sync(0xffffffffu, b2v[i], off);
            int   oj  = __shfl_xor_sync(0xffffffffu, bj[i], off);
            float nb2 = fminf(fmaxf(bv[i], ob), fminf(b2v[i], ob2));
            if (ob < bv[i]) { bv[i] = ob; bj[i] = oj; }
            b2v[i] = nb2;
        }
    }
    if ((lane & 3) == 0) {
#pragma unroll
        for (int i = 0; i < 4; i++) {
            int lr = (lane >> 2) + i * 8;
            s_bj[wid][lr] = bj[i];
            s_fl[wid][lr] = (b2v[i] - bv[i] < DELTA) ? 1 : 0;
        }
    }
    __syncwarp();

    // ---- per-row output: gather codeword, idx, flag ----
    {
        const int grow = wrow + lane;
        const int jv = s_bj[wid][lane];
        const float4* wr = (const float4*)(w + (size_t)jv * DIM);
        float4* orow = (float4*)(out + (size_t)grow * DIM);
#pragma unroll
        for (int k = 0; k < DIM / 4; k++) orow[k] = wr[k];
        if (out_idx) out_idx[grow] = (float)jv;
        if (s_fl[wid][lane]) {
            int slot = atomicAdd(&g_nflag, 1);
            g_flagrows[slot] = grow;
        }
    }
}

// ---------------- kernel 3: exact fp32 rescore of flagged rows (warp per row) ----------------
__global__ void cleanup_kernel(const float* __restrict__ x, const float* __restrict__ w,
                               float* __restrict__ out, float* __restrict__ out_idx) {
    const int nf = g_nflag;
    const int lane = threadIdx.x & 31;
    const int gwarp = (blockIdx.x * blockDim.x + threadIdx.x) >> 5;
    const int nwarps = (gridDim.x * blockDim.x) >> 5;

    for (int i = gwarp; i < nf; i += nwarps) {
        const int row = g_flagrows[i];
        float4 xr[DIM / 4];
        const float4* xp = (const float4*)(x + (size_t)row * DIM);
#pragma unroll
        for (int k = 0; k < DIM / 4; k++) xr[k] = xp[k];

        float best = CUDART_INF_F;
        int bj = 0x7fffffff;
        for (int j = lane; j < N_CODES; j += 32) {
            const float4* wp = (const float4*)(w + (size_t)j * DIM);
            float d0 = 0.f, d1 = 0.f, d2 = 0.f, d3 = 0.f;
#pragma unroll
            for (int k = 0; k < DIM / 4; k++) {
                float4 wv = wp[k];
                d0 = fmaf(xr[k].x, wv.x, d0);
                d1 = fmaf(xr[k].y, wv.y, d1);
                d2 = fmaf(xr[k].z, wv.z, d2);
                d3 = fmaf(xr[k].w, wv.w, d3);
            }
            float s = fmaf(-2.0f, (d0 + d1) + (d2 + d3), g_wsq[j]);
            if (s < best) { best = s; bj = j; }   // j increases per lane -> lowest idx kept
        }
#pragma unroll
        for (int off = 16; off; off >>= 1) {
            float ob = __shfl_down_sync(0xffffffffu, best, off);
            int   oj = __shfl_down_sync(0xffffffffu, bj, off);
            if (ob < best || (ob == best && oj < bj)) { best = ob; bj = oj; }
        }
        bj = __shfl_sync(0xffffffffu, bj, 0);

        const float2* wr = (const float2*)(w + (size_t)bj * DIM);
        float2* orow = (float2*)(out + (size_t)row * DIM);
        orow[lane] = wr[lane];
        if (lane == 0 && out_idx) out_idx[row] = (float)bj;
    }
}

// ---------------- launch ----------------
extern "C" void kernel_launch(void* const* d_in, const int* in_sizes, int n_in,
                              void* d_out, int out_size) {
    const float* x = (const float*)d_in[0];
    const float* w = (const float*)d_in[1];
    float* out = (float*)d_out;

    const int n_rows = in_sizes[0] / DIM;   // 65536

    float* out_idx = nullptr;
    if ((size_t)out_size >= (size_t)n_rows * DIM + (size_t)n_rows)
        out_idx = out + (size_t)n_rows * DIM;

    prep_kernel<<<(N_CODES + 255) / 256, 256>>>(w);
    vq_main<<<n_rows / ROWS_PER_CTA, BLOCK_THREADS>>>(x, w, out, out_idx);
    cleanup_kernel<<<128, 128>>>(x, w, out, out_idx);
}